// round 11
// baseline (speedup 1.0000x reference)
#include <cuda_runtime.h>
#include <cuda_bf16.h>
#include <math.h>
#include <stdint.h>

// Problem constants
#define BB 32
#define TT 512
#define WW 250
#define DD 768
#define GG 3072       // 4*D
#define MROWS 8000    // B*W
#define H2 1536       // 2*D
#define MP 8192       // padded M (32*256)

// fragment-block sizes (floats)
#define ABLKF 10240   // 40960 B per (mt,kc): 16 groups x 32 slots x 20 floats
#define BBLKF 5120    // 20480 B per (nt,kc):  8 groups x 32 slots x 20 floats
#define BUFF  15360   // A+B per kc

// ------------------- device scratch (static globals; no allocs) -------------------
__device__ float g_feat[MROWS * DD];
__device__ float g_pre0[MROWS * GG];
__device__ float g_pre1[MROWS * GG];
__device__ float g_h1[MROWS * H2];
__device__ float g_h2[MROWS * H2];
__device__ float g_emis[MROWS * 2];
__device__ float g_hT[2][2][DD][BB];         // [parity][dir][k][b]
__device__ float g_a3[32 * 144 * ABLKF];     // fragment-major split A blocks
__device__ float g_b3f[24 * 144 * BBLKF];    // fragment-major split W (fwd)
__device__ float g_b3r[24 * 144 * BBLKF];    // (rev)
__device__ float g_bpm0[GG];
__device__ float g_bpm1[GG];
__device__ int   g_first[MROWS];
__device__ unsigned char g_bp[BB][WW][2];
__device__ unsigned g_ccnt[2][8];            // per-dir per-chunk monotonic counters
__device__ int g_w64 = 0;

// ------------------- packed f32x2 helpers (LSTM) -------------------
typedef unsigned long long ull;
__device__ __forceinline__ ull fma2(ull a, ull b, ull c) {
    ull d;
    asm("fma.rn.f32x2 %0, %1, %2, %3;" : "=l"(d) : "l"(a), "l"(b), "l"(c));
    return d;
}
__device__ __forceinline__ ull packf2(float lo, float hi) {
    ull d;
    asm("mov.b64 %0, {%1, %2};" : "=l"(d)
        : "r"(__float_as_uint(lo)), "r"(__float_as_uint(hi)));
    return d;
}
__device__ __forceinline__ float2 unpackf2(ull v) {
    unsigned lo, hi;
    asm("mov.b64 {%0, %1}, %2;" : "=r"(lo), "=r"(hi) : "l"(v));
    return make_float2(__uint_as_float(lo), __uint_as_float(hi));
}

// ------------------- tf32 helpers -------------------
__device__ __forceinline__ float to_tf32(float v) {
    float r;
    asm("cvt.rna.tf32.f32 %0, %1;" : "=f"(r) : "f"(v));
    return r;
}

// ------------------- TMA / mbarrier helpers -------------------
__device__ __forceinline__ uint32_t smem_u32(const void* p) {
    uint32_t a;
    asm("{ .reg .u64 t; cvta.to.shared.u64 t, %1; cvt.u32.u64 %0, t; }"
        : "=r"(a) : "l"(p));
    return a;
}
__device__ __forceinline__ void mbar_init(uint32_t addr, uint32_t count) {
    asm volatile("mbarrier.init.shared.b64 [%0], %1;" :: "r"(addr), "r"(count) : "memory");
}
__device__ __forceinline__ void mbar_wait(uint32_t addr, uint32_t phase) {
    uint32_t done;
    do {
        asm volatile(
            "{\n\t.reg .pred p;\n\t"
            "mbarrier.try_wait.parity.acquire.cta.shared::cta.b64 p, [%1], %2, 0x989680;\n\t"
            "selp.b32 %0, 1, 0, p;\n\t}"
            : "=r"(done) : "r"(addr), "r"(phase) : "memory");
    } while (!done);
}
__device__ __forceinline__ void mbar_expect(uint32_t mbar, uint32_t bytes) {
    asm volatile("mbarrier.arrive.expect_tx.shared.b64 _, [%0], %1;"
                 :: "r"(mbar), "r"(bytes) : "memory");
}
__device__ __forceinline__ void bulk_cp(uint32_t mbar, uint32_t dst_smem,
                                        const void* src_gmem, uint32_t bytes) {
    asm volatile(
        "cp.async.bulk.shared::cluster.global.mbarrier::complete_tx::bytes "
        "[%0], [%1], %2, [%3];"
        :: "r"(dst_smem), "l"(src_gmem), "r"(bytes), "r"(mbar) : "memory");
}
__device__ __forceinline__ void bulk_st(void* gdst, uint32_t ssrc, uint32_t bytes) {
    asm volatile("cp.async.bulk.global.shared::cta.bulk_group [%0], [%1], %2;"
                 :: "l"(gdst), "r"(ssrc), "r"(bytes) : "memory");
}

// ------------------- int64 vs int32 detection -------------------
__global__ void detect_kernel(const int* __restrict__ w) {
    __shared__ int bad;
    if (threadIdx.x == 0) bad = 0;
    __syncthreads();
    for (int i = threadIdx.x; i < 8192; i += blockDim.x) {
        int v = w[2 * i + 1];
        if (v != 0 && v != -1) bad = 1;
    }
    __syncthreads();
    if (threadIdx.x == 0) g_w64 = bad ? 0 : 1;
}

// ------------------- first-subtoken index -------------------
__global__ void firstidx_kernel(const int* __restrict__ w) {
    int id = blockIdx.x * blockDim.x + threadIdx.x;
    if (id >= MROWS) return;
    int b = id / WW, ww = id % WW;
    int mul = g_w64 ? 2 : 1;
    const int* row = w + (size_t)b * TT * mul;
    int idx = TT - 1;
    for (int t = 0; t < TT; t++) {
        if (row[t * mul] == ww) { idx = t; break; }
    }
    g_first[id] = idx;
}

// ------------------- gather feat rows -------------------
__global__ void gather_kernel(const float* __restrict__ bert) {
    int row = blockIdx.x;
    int fi = g_first[row];
    int b = row / WW;
    const float4* src = (const float4*)(bert + ((size_t)b * TT + fi) * DD);
    float4* dst = (float4*)(g_feat + (size_t)row * DD);
    for (int i = threadIdx.x; i < DD / 4; i += blockDim.x) dst[i] = src[i];
}

// ------------------- splitA: fragment-major [hi|hi|lo] blocks -------------------
__global__ void splitA_frag(const float* __restrict__ src, float* __restrict__ dst,
                            int M, int K, int nkc)
{
    __shared__ float img[ABLKF];
    int tid = threadIdx.x;
    int kc = blockIdx.x, mt = blockIdx.y;
    int seg = (kc * 32) / K;
    int k0 = kc * 32 - seg * K;
    int m = mt * 256 + tid;

    float v[32];
    if (m < M) {
        const float4* s = (const float4*)(src + (size_t)m * K + k0);
#pragma unroll
        for (int p = 0; p < 8; p++) {
            float4 t = s[p];
            v[p * 4] = t.x; v[p * 4 + 1] = t.y; v[p * 4 + 2] = t.z; v[p * 4 + 3] = t.w;
        }
    } else {
#pragma unroll
        for (int p = 0; p < 32; p++) v[p] = 0.f;
    }

    int gid = tid & 7, half = (tid >> 3) & 1, i = (tid >> 4) & 3, m64 = tid >> 6;
#pragma unroll
    for (int kk = 0; kk < 32; kk++) {
        float hi = to_tf32(v[kk]);
        float ov = (seg < 2) ? hi : to_tf32(v[kk] - hi);
        int k8 = kk >> 3, rp = (kk >> 2) & 1, tg = kk & 3;
        img[(k8 * 4 + m64) * 640 + (gid * 4 + tg) * 20 + i * 4 + rp * 2 + half] = ov;
    }
    __syncthreads();
    if (tid == 0) {
        asm volatile("fence.proxy.async.shared::cta;" ::: "memory");
        bulk_st(dst + ((size_t)mt * nkc + kc) * ABLKF, smem_u32(img), ABLKF * 4);
        asm volatile("cp.async.bulk.commit_group;" ::: "memory");
        asm volatile("cp.async.bulk.wait_group 0;" ::: "memory");
    }
}

// ------------------- splitB: fragment-major [hi|lo|hi] permuted W blocks -------------------
__global__ void splitB_frag(const float* __restrict__ w, const float* __restrict__ bias,
                            float* __restrict__ dst, float* __restrict__ dstb,
                            int K, int nkc)
{
    __shared__ float img[BBLKF];
    int tid = threadIdx.x;
    int kc = blockIdx.x, nt = blockIdx.y;
    int seg = (kc * 32) / K;
    int k0 = kc * 32 - seg * K;
    int nloc = tid >> 1, khalf = tid & 1;
    int np = nt * 128 + nloc;
    int c = np / 48, rr = np % 48, g = rr / 12, u = rr % 12;
    int srow = g * DD + c * 12 + u;

    float v[16];
    const float4* s = (const float4*)(w + (size_t)srow * K + k0 + khalf * 16);
#pragma unroll
    for (int p = 0; p < 4; p++) {
        float4 t = s[p];
        v[p * 4] = t.x; v[p * 4 + 1] = t.y; v[p * 4 + 2] = t.z; v[p * 4 + 3] = t.w;
    }
    if (kc == 0 && khalf == 0) dstb[np] = bias[srow];

    int n64 = nloc >> 6, j = (nloc >> 3) & 7, gid = nloc & 7;
#pragma unroll
    for (int q = 0; q < 16; q++) {
        int kk = khalf * 16 + q;
        float hi = to_tf32(v[q]);
        float ov = (seg == 1) ? to_tf32(v[q] - hi) : hi;
        int k8 = kk >> 3, rp = (kk >> 2) & 1, tg = kk & 3;
        img[(k8 * 2 + n64) * 640 + (gid * 4 + tg) * 20 + j * 2 + rp] = ov;
    }
    __syncthreads();
    if (tid == 0) {
        asm volatile("fence.proxy.async.shared::cta;" ::: "memory");
        bulk_st(dst + ((size_t)nt * nkc + kc) * BBLKF, smem_u32(img), BBLKF * 4);
        asm volatile("cp.async.bulk.commit_group;" ::: "memory");
        asm volatile("cp.async.bulk.wait_group 0;" ::: "memory");
    }
}

// ------------------- fragment-fed tf32 tensor-core GEMM -------------------
__global__ __launch_bounds__(256) void mma_frag_kernel(
    const float* __restrict__ AF, const float* __restrict__ BF,
    const float* __restrict__ bias, float* __restrict__ C,
    int M, int nkc)
{
    extern __shared__ float gsm[];
    __shared__ __align__(8) unsigned long long mb[2];
    int tid = threadIdx.x;
    int warp = tid >> 5, lane = tid & 31;
    int nt = blockIdx.x, mt = blockIdx.y;
    int warp_m = (warp >> 1) * 64, warp_n = (warp & 1) * 64;
    int m64w = warp >> 1, n64w = warp & 1;
    int gid = lane >> 2, tig = lane & 3;

    uint32_t mb0 = smem_u32(&mb[0]);
    uint32_t sm0 = smem_u32(gsm);

    if (tid == 0) { mbar_init(mb0, 1); mbar_init(mb0 + 8, 1); }
    __syncthreads();

    const float* Abase = AF + (size_t)mt * nkc * ABLKF;
    const float* Bbase = BF + (size_t)nt * nkc * BBLKF;

    if (tid == 0) {
        mbar_expect(mb0, BUFF * 4);
        bulk_cp(mb0, sm0, Abase, ABLKF * 4);
        bulk_cp(mb0, sm0 + ABLKF * 4, Bbase, BBLKF * 4);
    }

    float d[4][8][4];
#pragma unroll
    for (int i = 0; i < 4; i++)
#pragma unroll
        for (int j = 0; j < 8; j++)
#pragma unroll
            for (int q = 0; q < 4; q++) d[i][j][q] = 0.f;

    uint32_t ph = 0;
    int buf = 0;
    for (int kc = 0; kc < nkc; kc++) {
        mbar_wait(mb0 + buf * 8, (ph >> buf) & 1u);
        ph ^= (1u << buf);
        __syncthreads();
        if (tid == 0 && kc + 1 < nkc) {
            int nb = buf ^ 1;
            mbar_expect(mb0 + nb * 8, BUFF * 4);
            bulk_cp(mb0 + nb * 8, sm0 + nb * BUFF * 4,
                    Abase + (size_t)(kc + 1) * ABLKF, ABLKF * 4);
            bulk_cp(mb0 + nb * 8, sm0 + nb * BUFF * 4 + ABLKF * 4,
                    Bbase + (size_t)(kc + 1) * BBLKF, BBLKF * 4);
        }
        const float* Ab = gsm + buf * BUFF;
        const float* Bb = Ab + ABLKF;
#pragma unroll
        for (int k8 = 0; k8 < 4; k8++) {
            float af[16], bf[16];
            const float* ap = Ab + (k8 * 4 + m64w) * 640 + lane * 20;
            const float* bp = Bb + (k8 * 2 + n64w) * 640 + lane * 20;
#pragma unroll
            for (int p = 0; p < 4; p++) {
                *(float4*)&af[p * 4] = *(const float4*)(ap + p * 4);
                *(float4*)&bf[p * 4] = *(const float4*)(bp + p * 4);
            }
#pragma unroll
            for (int i = 0; i < 4; i++) {
#pragma unroll
                for (int j = 0; j < 8; j++) {
                    asm("mma.sync.aligned.m16n8k8.row.col.f32.tf32.tf32.f32 "
                        "{%0,%1,%2,%3}, {%4,%5,%6,%7}, {%8,%9}, {%0,%1,%2,%3};"
                        : "+f"(d[i][j][0]), "+f"(d[i][j][1]),
                          "+f"(d[i][j][2]), "+f"(d[i][j][3])
                        : "r"(__float_as_uint(af[i * 4 + 0])),
                          "r"(__float_as_uint(af[i * 4 + 1])),
                          "r"(__float_as_uint(af[i * 4 + 2])),
                          "r"(__float_as_uint(af[i * 4 + 3])),
                          "r"(__float_as_uint(bf[j * 2 + 0])),
                          "r"(__float_as_uint(bf[j * 2 + 1])));
                }
            }
        }
        buf ^= 1;
    }

#pragma unroll
    for (int i = 0; i < 4; i++) {
        int mr0 = mt * 256 + warp_m + i * 16 + gid;
        int mr1 = mr0 + 8;
#pragma unroll
        for (int j = 0; j < 8; j++) {
            int nc = nt * 128 + warp_n + j * 8 + tig * 2;
            float b0 = bias[nc], b1 = bias[nc + 1];
            if (mr0 < M) {
                C[(size_t)mr0 * GG + nc]     = d[i][j][0] + b0;
                C[(size_t)mr0 * GG + nc + 1] = d[i][j][1] + b1;
            }
            if (mr1 < M) {
                C[(size_t)mr1 * GG + nc]     = d[i][j][2] + b0;
                C[(size_t)mr1 * GG + nc + 1] = d[i][j][3] + b1;
            }
        }
    }
}

// ------------------- persistent LSTM: chunk-pipelined producer/consumer -------------------
#define HCHUNK_BYTES (128 * BB * 4)
#define PRE_SLICE_B (48 * BB * 4)

__global__ void reset_cnt_kernel() {
    if (threadIdx.x < 16) ((unsigned*)g_ccnt)[threadIdx.x] = 0;
}

// wait until *p >= need (monotonic counter), then acquire-fence
__device__ __forceinline__ void wait_cnt(const unsigned* p, unsigned need) {
    if (*(volatile const unsigned*)p < need) {
        while (*(volatile const unsigned*)p < need) __nanosleep(32);
    }
    __threadfence();
}

__global__ __launch_bounds__(256) void lstm_persist_kernel(
    const float* __restrict__ preF, const float* __restrict__ preR,
    const float* __restrict__ whhF, const float* __restrict__ whhR,
    float* __restrict__ hout)
{
    extern __shared__ float sm[];
    float* w2_s   = sm;                      // 48*768 interleaved row-pairs
    float* h_s    = w2_s + 48 * DD;          // 3*128*32 ring
    float* gate_s = h_s + 3 * 128 * BB;      // 32*48  [b][r]
    float* c_s    = gate_s + 32 * 48;        // 384
    float* pre_s  = c_s + 384;               // 2*1536 [slot][b*48+r]
    __shared__ __align__(8) unsigned long long mbar_arr[5];

    int tid = threadIdx.x, bid = blockIdx.x;
    int dir = bid >> 6;
    int cta = bid & 63;
    int U0 = cta * 12;
    const float* whh = dir ? whhR : whhF;
    const float* pre = dir ? preR : preF;

    int warp = tid >> 5, lane = tid & 31;
    int r0 = warp * 6;
    int p0 = warp * 3;

    // chunks this CTA's units write, and per-chunk writer counts
    int c_lo = U0 / 128, c_hi = (U0 + 11) / 128;
    unsigned* mycnt = &g_ccnt[dir][0];

    uint32_t mbar0 = smem_u32(&mbar_arr[0]);
    uint32_t hsm0  = smem_u32(h_s);
    uint32_t psm0  = smem_u32(pre_s);

    if (tid == 0) {
        for (int i = 0; i < 5; i++) mbar_init(mbar0 + i * 8, 1);
        int t0 = dir ? (WW - 1) : 0;
        mbar_expect(mbar0 + 3 * 8, PRE_SLICE_B);
        for (int b = 0; b < BB; b++)
            bulk_cp(mbar0 + 3 * 8, psm0 + b * 192,
                    pre + ((size_t)b * WW + t0) * GG + cta * 48, 192);
    }

    for (int idx = tid; idx < 48 * (DD / 4); idx += 256) {
        int r = idx / (DD / 4), k4 = idx % (DD / 4);
        int g = r / 12, u = r % 12;
        float4 v = *(const float4*)(whh + ((size_t)(g * DD + U0 + u)) * DD + k4 * 4);
        float* base = &w2_s[(r >> 1) * (2 * DD) + (k4 * 4) * 2 + (r & 1)];
        base[0] = v.x; base[2] = v.y; base[4] = v.z; base[6] = v.w;
    }
    for (int idx = tid; idx < 12 * BB; idx += 256) c_s[idx] = 0.f;
    __syncthreads();

    uint32_t phbits = 0;
    uint32_t preph = 0;

    for (int s = 0; s < WW; ++s) {
        int t = dir ? (WW - 1 - s) : s;

        if (tid == 0 && s + 1 < WW) {
            int tn = dir ? (WW - 2 - s) : (s + 1);
            int slot = (s + 1) & 1;
            mbar_expect(mbar0 + (3 + slot) * 8, PRE_SLICE_B);
            for (int b = 0; b < BB; b++)
                bulk_cp(mbar0 + (3 + slot) * 8, psm0 + slot * PRE_SLICE_B + b * 192,
                        pre + ((size_t)b * WW + tn) * GG + cta * 48, 192);
        }

        ull acc2[3] = {0ull, 0ull, 0ull};

        if (s > 0) {
            const char* hsrc = (const char*)&g_hT[(s - 1) & 1][dir][0][0];
            if (tid == 0) {
                // chunk 0: W[0] = 127/12 - 0 + 1 = 11 writers
                wait_cnt(mycnt + 0, 11u * (unsigned)s);
                mbar_expect(mbar0 + 0, HCHUNK_BYTES);
                bulk_cp(mbar0 + 0, hsm0, hsrc, HCHUNK_BYTES);
                // chunk 1
                {
                    unsigned Wc = (unsigned)((128 + 127) / 12 - 128 / 12 + 1);
                    wait_cnt(mycnt + 1, Wc * (unsigned)s);
                }
                mbar_expect(mbar0 + 8, HCHUNK_BYTES);
                bulk_cp(mbar0 + 8, hsm0 + HCHUNK_BYTES, hsrc + HCHUNK_BYTES, HCHUNK_BYTES);
            }
#pragma unroll 1
            for (int c = 0; c < 6; c++) {
                int slot = c % 3;
                mbar_wait(mbar0 + slot * 8, (phbits >> slot) & 1u);
                phbits ^= (1u << slot);
                __syncthreads();   // prior consumers of this slot done -> refillable
                if (tid == 0 && c < 4) {
                    int cn = c + 2;
                    unsigned Wc = (unsigned)((128 * cn + 127) / 12 - (128 * cn) / 12 + 1);
                    wait_cnt(mycnt + cn, Wc * (unsigned)s);
                    int s2 = cn % 3;
                    mbar_expect(mbar0 + s2 * 8, HCHUNK_BYTES);
                    bulk_cp(mbar0 + s2 * 8, hsm0 + s2 * HCHUNK_BYTES,
                            hsrc + (size_t)cn * HCHUNK_BYTES, HCHUNK_BYTES);
                }
                const float* hb = h_s + slot * (128 * BB);
#pragma unroll 4
                for (int kk = 0; kk < 128; kk += 4) {
                    float h0 = hb[(kk + 0) * BB + lane];
                    float h1 = hb[(kk + 1) * BB + lane];
                    float h2v = hb[(kk + 2) * BB + lane];
                    float h3 = hb[(kk + 3) * BB + lane];
                    ull hp0 = packf2(h0, h0), hp1 = packf2(h1, h1);
                    ull hp2 = packf2(h2v, h2v), hp3 = packf2(h3, h3);
#pragma unroll
                    for (int j2 = 0; j2 < 3; j2++) {
                        const float* wb = &w2_s[(p0 + j2) * (2 * DD) + (c * 128 + kk) * 2];
                        ulonglong2 wv0 = *(const ulonglong2*)(wb);
                        ulonglong2 wv1 = *(const ulonglong2*)(wb + 4);
                        acc2[j2] = fma2(wv0.x, hp0, acc2[j2]);
                        acc2[j2] = fma2(wv0.y, hp1, acc2[j2]);
                        acc2[j2] = fma2(wv1.x, hp2, acc2[j2]);
                        acc2[j2] = fma2(wv1.y, hp3, acc2[j2]);
                    }
                }
            }
        }

#pragma unroll
        for (int j2 = 0; j2 < 3; j2++) {
            float2 v = unpackf2(acc2[j2]);
            gate_s[lane * 48 + r0 + 2 * j2]     = v.x;
            gate_s[lane * 48 + r0 + 2 * j2 + 1] = v.y;
        }
        {
            int slot = s & 1;
            mbar_wait(mbar0 + (3 + slot) * 8, (preph >> slot) & 1u);
            preph ^= (1u << slot);
        }
        __syncthreads();

        const float* ps = pre_s + (s & 1) * (48 * BB);
        for (int item = tid; item < 12 * BB; item += 256) {
            int b = item / 12, u = item % 12;
            float gi = ps[b * 48 + 0 * 12 + u] + gate_s[b * 48 + 0 * 12 + u];
            float gf = ps[b * 48 + 1 * 12 + u] + gate_s[b * 48 + 1 * 12 + u];
            float gg = ps[b * 48 + 2 * 12 + u] + gate_s[b * 48 + 2 * 12 + u];
            float go = ps[b * 48 + 3 * 12 + u] + gate_s[b * 48 + 3 * 12 + u];
            float iv = 1.f / (1.f + expf(-gi));
            float fv = 1.f / (1.f + expf(-gf));
            float gv = tanhf(gg);
            float ov = 1.f / (1.f + expf(-go));
            float cc = fv * c_s[item] + iv * gv;
            c_s[item] = cc;
            float hh = ov * tanhf(cc);
            __stcg(&g_hT[s & 1][dir][U0 + u][b], hh);
            hout[((size_t)(b * WW + t)) * H2 + dir * DD + U0 + u] = hh;
        }

        // publish: release-fence then bump chunk counters this CTA writes
        __threadfence();
        __syncthreads();
        if (tid == 0) {
            atomicAdd(mycnt + c_lo, 1u);
            if (c_hi != c_lo) atomicAdd(mycnt + c_hi, 1u);
        }
    }
}

// ------------------- emissions: linear (NT=2) + softmax -------------------
__global__ void emis_kernel(const float* __restrict__ h2,
                            const float* __restrict__ wlin,
                            const float* __restrict__ blin,
                            float* __restrict__ out)
{
    int row = blockIdx.x * 8 + (threadIdx.x >> 5);
    int lane = threadIdx.x & 31;
    if (row >= MROWS) return;
    const float4* hr = (const float4*)(h2 + (size_t)row * H2);
    const float4* w0 = (const float4*)(wlin);
    const float4* w1 = (const float4*)(wlin + H2);
    float a0 = 0.f, a1 = 0.f;
    for (int i = lane; i < H2 / 4; i += 32) {
        float4 hv = hr[i], x0 = w0[i], x1 = w1[i];
        a0 += hv.x * x0.x + hv.y * x0.y + hv.z * x0.z + hv.w * x0.w;
        a1 += hv.x * x1.x + hv.y * x1.y + hv.z * x1.z + hv.w * x1.w;
    }
#pragma unroll
    for (int o = 16; o; o >>= 1) {
        a0 += __shfl_down_sync(0xffffffffu, a0, o);
        a1 += __shfl_down_sync(0xffffffffu, a1, o);
    }
    if (lane == 0) {
        float l0 = a0 + blin[0], l1 = a1 + blin[1];
        float m = fmaxf(l0, l1);
        float e0 = expf(l0 - m), e1 = expf(l1 - m);
        float inv = 1.f / (e0 + e1);
        float p0 = e0 * inv, p1 = e1 * inv;
        g_emis[row * 2] = p0; g_emis[row * 2 + 1] = p1;
        out[MROWS + row * 2] = p0; out[MROWS + row * 2 + 1] = p1;
    }
}

// ------------------- CRF -------------------
__device__ __forceinline__ float lse2(float x, float y) {
    float m = fmaxf(x, y);
    return m + log1pf(expf(fminf(x, y) - m));
}

__global__ void crf_llh_kernel(const int* __restrict__ labels,
                               const float* __restrict__ start,
                               const float* __restrict__ endv,
                               const float* __restrict__ trans,
                               float* __restrict__ out)
{
    int b = threadIdx.x;
    __shared__ float red[BB];
    int mul = g_w64 ? 2 : 1;
    const int* lab = labels + (size_t)b * WW * mul;
    float t00 = trans[0], t01 = trans[1], t10 = trans[2], t11 = trans[3];

    int prev = lab[0];
    float num = start[prev];
    for (int s = 0; s < WW; s++) {
        int tg = lab[s * mul];
        num += g_emis[(b * WW + s) * 2 + tg];
        if (s > 0) num += trans[prev * 2 + tg];
        prev = tg;
    }
    num += endv[prev];

    float a0 = start[0] + g_emis[(b * WW) * 2 + 0];
    float a1 = start[1] + g_emis[(b * WW) * 2 + 1];
    for (int s = 1; s < WW; s++) {
        float e0 = g_emis[(b * WW + s) * 2 + 0];
        float e1 = g_emis[(b * WW + s) * 2 + 1];
        float x0 = lse2(a0 + t00, a1 + t10) + e0;
        float x1 = lse2(a0 + t01, a1 + t11) + e1;
        a0 = x0; a1 = x1;
    }
    float logZ = lse2(a0 + endv[0], a1 + endv[1]);
    red[b] = num - logZ;
    __syncthreads();
    if (b == 0) {
        float sum = 0.f;
        for (int i = 0; i < BB; i++) sum += red[i];
        out[MROWS + MROWS * 2] = -(sum / (float)BB);
    }
}

__global__ void crf_decode_kernel(const float* __restrict__ start,
                                  const float* __restrict__ endv,
                                  const float* __restrict__ trans,
                                  float* __restrict__ out)
{
    int b = threadIdx.x;
    float t00 = trans[0], t01 = trans[1], t10 = trans[2], t11 = trans[3];
    float s0 = start[0] + g_emis[(b * WW) * 2 + 0];
    float s1 = start[1] + g_emis[(b * WW) * 2 + 1];
    for (int s = 1; s < WW; s++) {
        float c00 = s0 + t00, c10 = s1 + t10;
        float c01 = s0 + t01, c11 = s1 + t11;
        unsigned char bp0 = (c10 > c00) ? 1 : 0;
        unsigned char bp1 = (c11 > c01) ? 1 : 0;
        float e0 = g_emis[(b * WW + s) * 2 + 0];
        float e1 = g_emis[(b * WW + s) * 2 + 1];
        float n0 = fmaxf(c00, c10) + e0;
        float n1 = fmaxf(c01, c11) + e1;
        g_bp[b][s][0] = bp0; g_bp[b][s][1] = bp1;
        s0 = n0; s1 = n1;
    }
    int tag = (s1 + endv[1] > s0 + endv[0]) ? 1 : 0;
    out[b * WW + (WW - 1)] = (float)tag;
    for (int s = WW - 1; s >= 1; s--) {
        tag = (int)g_bp[b][s][tag];
        out[b * WW + (s - 1)] = (float)tag;
    }
}

// ------------------- host launcher -------------------
extern "C" void kernel_launch(void* const* d_in, const int* in_sizes, int n_in,
                              void* d_out, int out_size)
{
    const float* bert      = (const float*)d_in[0];
    const int*   words     = (const int*)d_in[1];
    const int*   labels    = (const int*)d_in[2];
    const float* w_ih_l0   = (const float*)d_in[3];
    const float* w_hh_l0   = (const float*)d_in[4];
    const float* b_l0      = (const float*)d_in[5];
    const float* w_ih_l0r  = (const float*)d_in[6];
    const float* w_hh_l0r  = (const float*)d_in[7];
    const float* b_l0r     = (const float*)d_in[8];
    const float* w_ih_l1   = (const float*)d_in[9];
    const float* w_hh_l1   = (const float*)d_in[10];
    const float* b_l1      = (const float*)d_in[11];
    const float* w_ih_l1r  = (const float*)d_in[12];
    const float* w_hh_l1r  = (const float*)d_in[13];
    const float* b_l1r     = (const float*)d_in[14];
    const float* w_lin     = (const float*)d_in[15];
    const float* b_lin     = (const float*)d_in[16];
    const float* crf_start = (const float*)d_in[17];
    const float* crf_end   = (const float*)d_in[18];
    const float* crf_trans = (const float*)d_in[19];
    float* out = (float*)d_out;

    float *pfeat, *ppre0, *ppre1, *ph1, *ph2, *pa3, *pb3f, *pb3r, *pbp0, *pbp1;
    cudaGetSymbolAddress((void**)&pfeat, g_feat);
    cudaGetSymbolAddress((void**)&ppre0, g_pre0);
    cudaGetSymbolAddress((void**)&ppre1, g_pre1);
    cudaGetSymbolAddress((void**)&ph1, g_h1);
    cudaGetSymbolAddress((void**)&ph2, g_h2);
    cudaGetSymbolAddress((void**)&pa3, g_a3);
    cudaGetSymbolAddress((void**)&pb3f, g_b3f);
    cudaGetSymbolAddress((void**)&pb3r, g_b3r);
    cudaGetSymbolAddress((void**)&pbp0, g_bpm0);
    cudaGetSymbolAddress((void**)&pbp1, g_bpm1);

    const int lstm_smem = (48 * DD + 3 * 128 * BB + 32 * 48 + 384 + 2 * 48 * BB) * 4;
    cudaFuncSetAttribute(lstm_persist_kernel,
                         cudaFuncAttributeMaxDynamicSharedMemorySize, lstm_smem);
    const int gemm_smem = 2 * BUFF * 4;   // 122880
    cudaFuncSetAttribute(mma_frag_kernel,
                         cudaFuncAttributeMaxDynamicSharedMemorySize, gemm_smem);

    detect_kernel<<<1, 256>>>(words);
    firstidx_kernel<<<(MROWS + 255) / 256, 256>>>(words);
    gather_kernel<<<MROWS, 192>>>(bert);

    dim3 ggrid(GG / 128, MP / 256);   // (24, 32)

    // ---- layer 0 projections (K=768, K3=2304, nkc=72) ----
    {
        int nkc = 3 * DD / 32;
        splitA_frag<<<dim3(nkc, MP / 256), 256>>>(pfeat, pa3, MROWS, DD, nkc);
        splitB_frag<<<dim3(nkc, GG / 128), 256>>>(w_ih_l0,  b_l0,  pb3f, pbp0, DD, nkc);
        splitB_frag<<<dim3(nkc, GG / 128), 256>>>(w_ih_l0r, b_l0r, pb3r, pbp1, DD, nkc);
        mma_frag_kernel<<<ggrid, 256, gemm_smem>>>(pa3, pb3f, pbp0, ppre0, MROWS, nkc);
        mma_frag_kernel<<<ggrid, 256, gemm_smem>>>(pa3, pb3r, pbp1, ppre1, MROWS, nkc);
    }

    reset_cnt_kernel<<<1, 32>>>();
    lstm_persist_kernel<<<128, 256, lstm_smem>>>(ppre0, ppre1, w_hh_l0, w_hh_l0r, ph1);

    // ---- layer 1 projections (K=1536, K3=4608, nkc=144) ----
    {
        int nkc = 3 * H2 / 32;
        splitA_frag<<<dim3(nkc, MP / 256), 256>>>(ph1, pa3, MROWS, H2, nkc);
        splitB_frag<<<dim3(nkc, GG / 128), 256>>>(w_ih_l1,  b_l1,  pb3f, pbp0, H2, nkc);
        splitB_frag<<<dim3(nkc, GG / 128), 256>>>(w_ih_l1r, b_l1r, pb3r, pbp1, H2, nkc);
        mma_frag_kernel<<<ggrid, 256, gemm_smem>>>(pa3, pb3f, pbp0, ppre0, MROWS, nkc);
        mma_frag_kernel<<<ggrid, 256, gemm_smem>>>(pa3, pb3r, pbp1, ppre1, MROWS, nkc);
    }

    reset_cnt_kernel<<<1, 32>>>();
    lstm_persist_kernel<<<128, 256, lstm_smem>>>(ppre0, ppre1, w_hh_l1, w_hh_l1r, ph2);

    emis_kernel<<<MROWS / 8, 256>>>(ph2, w_lin, b_lin, out);
    crf_llh_kernel<<<1, BB>>>(labels, crf_start, crf_end, crf_trans, out);
    crf_decode_kernel<<<1, BB>>>(crf_start, crf_end, crf_trans, out);
}

// round 12
// speedup vs baseline: 1.1011x; 1.1011x over previous
#include <cuda_runtime.h>
#include <cuda_bf16.h>
#include <math.h>
#include <stdint.h>

// Problem constants
#define BB 32
#define TT 512
#define WW 250
#define DD 768
#define GG 3072       // 4*D
#define MROWS 8000    // B*W
#define H2 1536       // 2*D
#define MP 8192       // padded M (32*256)

// fragment-block sizes (floats)
#define ABLKF 10240   // 40960 B per (mt,kc): 16 groups x 32 slots x 20 floats
#define BBLKF 5120    // 20480 B per (nt,kc):  8 groups x 32 slots x 20 floats
#define BUFF  15360   // A+B per kc

// ------------------- device scratch (static globals; no allocs) -------------------
__device__ float g_feat[MROWS * DD];
__device__ float g_pre0[MROWS * GG];
__device__ float g_pre1[MROWS * GG];
__device__ float g_h1[MROWS * H2];
__device__ float g_h2[MROWS * H2];
__device__ float g_emis[MROWS * 2];
__device__ float g_hT[2][2][DD][BB];         // [parity][dir][k][b]
__device__ float g_a3[32 * 144 * ABLKF];     // fragment-major split A blocks
__device__ float g_b3f[24 * 144 * BBLKF];    // fragment-major split W (fwd)
__device__ float g_b3r[24 * 144 * BBLKF];    // (rev)
__device__ float g_bpm0[GG];
__device__ float g_bpm1[GG];
__device__ int   g_first[MROWS];
__device__ unsigned char g_bp[BB][WW][2];
__device__ unsigned g_cnt[2] = {0, 0};       // per-dir barrier count
__device__ unsigned g_gen[2] = {0, 0};       // per-dir barrier generation
__device__ int g_w64 = 0;

// ------------------- packed f32x2 helpers (LSTM) -------------------
typedef unsigned long long ull;
__device__ __forceinline__ ull fma2(ull a, ull b, ull c) {
    ull d;
    asm("fma.rn.f32x2 %0, %1, %2, %3;" : "=l"(d) : "l"(a), "l"(b), "l"(c));
    return d;
}
__device__ __forceinline__ ull packf2(float lo, float hi) {
    ull d;
    asm("mov.b64 %0, {%1, %2};" : "=l"(d)
        : "r"(__float_as_uint(lo)), "r"(__float_as_uint(hi)));
    return d;
}
__device__ __forceinline__ float2 unpackf2(ull v) {
    unsigned lo, hi;
    asm("mov.b64 {%0, %1}, %2;" : "=r"(lo), "=r"(hi) : "l"(v));
    return make_float2(__uint_as_float(lo), __uint_as_float(hi));
}

// ------------------- tf32 helpers -------------------
__device__ __forceinline__ float to_tf32(float v) {
    float r;
    asm("cvt.rna.tf32.f32 %0, %1;" : "=f"(r) : "f"(v));
    return r;
}

// ------------------- TMA / mbarrier helpers -------------------
__device__ __forceinline__ uint32_t smem_u32(const void* p) {
    uint32_t a;
    asm("{ .reg .u64 t; cvta.to.shared.u64 t, %1; cvt.u32.u64 %0, t; }"
        : "=r"(a) : "l"(p));
    return a;
}
__device__ __forceinline__ void mbar_init(uint32_t addr, uint32_t count) {
    asm volatile("mbarrier.init.shared.b64 [%0], %1;" :: "r"(addr), "r"(count) : "memory");
}
__device__ __forceinline__ void mbar_wait(uint32_t addr, uint32_t phase) {
    uint32_t done;
    do {
        asm volatile(
            "{\n\t.reg .pred p;\n\t"
            "mbarrier.try_wait.parity.acquire.cta.shared::cta.b64 p, [%1], %2, 0x989680;\n\t"
            "selp.b32 %0, 1, 0, p;\n\t}"
            : "=r"(done) : "r"(addr), "r"(phase) : "memory");
    } while (!done);
}
__device__ __forceinline__ void mbar_expect(uint32_t mbar, uint32_t bytes) {
    asm volatile("mbarrier.arrive.expect_tx.shared.b64 _, [%0], %1;"
                 :: "r"(mbar), "r"(bytes) : "memory");
}
__device__ __forceinline__ void bulk_cp(uint32_t mbar, uint32_t dst_smem,
                                        const void* src_gmem, uint32_t bytes) {
    asm volatile(
        "cp.async.bulk.shared::cluster.global.mbarrier::complete_tx::bytes "
        "[%0], [%1], %2, [%3];"
        :: "r"(dst_smem), "l"(src_gmem), "r"(bytes), "r"(mbar) : "memory");
}
__device__ __forceinline__ void bulk_st(void* gdst, uint32_t ssrc, uint32_t bytes) {
    asm volatile("cp.async.bulk.global.shared::cta.bulk_group [%0], [%1], %2;"
                 :: "l"(gdst), "r"(ssrc), "r"(bytes) : "memory");
}

// ------------------- int64 vs int32 detection -------------------
__global__ void detect_kernel(const int* __restrict__ w) {
    __shared__ int bad;
    if (threadIdx.x == 0) bad = 0;
    __syncthreads();
    for (int i = threadIdx.x; i < 8192; i += blockDim.x) {
        int v = w[2 * i + 1];
        if (v != 0 && v != -1) bad = 1;
    }
    __syncthreads();
    if (threadIdx.x == 0) g_w64 = bad ? 0 : 1;
}

// ------------------- first-subtoken index -------------------
__global__ void firstidx_kernel(const int* __restrict__ w) {
    int id = blockIdx.x * blockDim.x + threadIdx.x;
    if (id >= MROWS) return;
    int b = id / WW, ww = id % WW;
    int mul = g_w64 ? 2 : 1;
    const int* row = w + (size_t)b * TT * mul;
    int idx = TT - 1;
    for (int t = 0; t < TT; t++) {
        if (row[t * mul] == ww) { idx = t; break; }
    }
    g_first[id] = idx;
}

// ------------------- gather feat rows -------------------
__global__ void gather_kernel(const float* __restrict__ bert) {
    int row = blockIdx.x;
    int fi = g_first[row];
    int b = row / WW;
    const float4* src = (const float4*)(bert + ((size_t)b * TT + fi) * DD);
    float4* dst = (float4*)(g_feat + (size_t)row * DD);
    for (int i = threadIdx.x; i < DD / 4; i += blockDim.x) dst[i] = src[i];
}

// ------------------- splitA: fragment-major [hi|hi|lo] blocks -------------------
__global__ void splitA_frag(const float* __restrict__ src, float* __restrict__ dst,
                            int M, int K, int nkc)
{
    __shared__ float img[ABLKF];
    int tid = threadIdx.x;
    int kc = blockIdx.x, mt = blockIdx.y;
    int seg = (kc * 32) / K;
    int k0 = kc * 32 - seg * K;
    int m = mt * 256 + tid;

    float v[32];
    if (m < M) {
        const float4* s = (const float4*)(src + (size_t)m * K + k0);
#pragma unroll
        for (int p = 0; p < 8; p++) {
            float4 t = s[p];
            v[p * 4] = t.x; v[p * 4 + 1] = t.y; v[p * 4 + 2] = t.z; v[p * 4 + 3] = t.w;
        }
    } else {
#pragma unroll
        for (int p = 0; p < 32; p++) v[p] = 0.f;
    }

    int gid = tid & 7, half = (tid >> 3) & 1, i = (tid >> 4) & 3, m64 = tid >> 6;
#pragma unroll
    for (int kk = 0; kk < 32; kk++) {
        float hi = to_tf32(v[kk]);
        float ov = (seg < 2) ? hi : to_tf32(v[kk] - hi);
        int k8 = kk >> 3, rp = (kk >> 2) & 1, tg = kk & 3;
        img[(k8 * 4 + m64) * 640 + (gid * 4 + tg) * 20 + i * 4 + rp * 2 + half] = ov;
    }
    __syncthreads();
    if (tid == 0) {
        asm volatile("fence.proxy.async.shared::cta;" ::: "memory");
        bulk_st(dst + ((size_t)mt * nkc + kc) * ABLKF, smem_u32(img), ABLKF * 4);
        asm volatile("cp.async.bulk.commit_group;" ::: "memory");
        asm volatile("cp.async.bulk.wait_group 0;" ::: "memory");
    }
}

// ------------------- splitB: fragment-major [hi|lo|hi] permuted W blocks -------------------
__global__ void splitB_frag(const float* __restrict__ w, const float* __restrict__ bias,
                            float* __restrict__ dst, float* __restrict__ dstb,
                            int K, int nkc)
{
    __shared__ float img[BBLKF];
    int tid = threadIdx.x;
    int kc = blockIdx.x, nt = blockIdx.y;
    int seg = (kc * 32) / K;
    int k0 = kc * 32 - seg * K;
    int nloc = tid >> 1, khalf = tid & 1;
    int np = nt * 128 + nloc;
    int c = np / 48, rr = np % 48, g = rr / 12, u = rr % 12;
    int srow = g * DD + c * 12 + u;

    float v[16];
    const float4* s = (const float4*)(w + (size_t)srow * K + k0 + khalf * 16);
#pragma unroll
    for (int p = 0; p < 4; p++) {
        float4 t = s[p];
        v[p * 4] = t.x; v[p * 4 + 1] = t.y; v[p * 4 + 2] = t.z; v[p * 4 + 3] = t.w;
    }
    if (kc == 0 && khalf == 0) dstb[np] = bias[srow];

    int n64 = nloc >> 6, j = (nloc >> 3) & 7, gid = nloc & 7;
#pragma unroll
    for (int q = 0; q < 16; q++) {
        int kk = khalf * 16 + q;
        float hi = to_tf32(v[q]);
        float ov = (seg == 1) ? to_tf32(v[q] - hi) : hi;
        int k8 = kk >> 3, rp = (kk >> 2) & 1, tg = kk & 3;
        img[(k8 * 2 + n64) * 640 + (gid * 4 + tg) * 20 + j * 2 + rp] = ov;
    }
    __syncthreads();
    if (tid == 0) {
        asm volatile("fence.proxy.async.shared::cta;" ::: "memory");
        bulk_st(dst + ((size_t)nt * nkc + kc) * BBLKF, smem_u32(img), BBLKF * 4);
        asm volatile("cp.async.bulk.commit_group;" ::: "memory");
        asm volatile("cp.async.bulk.wait_group 0;" ::: "memory");
    }
}

// ------------------- fragment-fed tf32 tensor-core GEMM -------------------
__global__ __launch_bounds__(256) void mma_frag_kernel(
    const float* __restrict__ AF, const float* __restrict__ BF,
    const float* __restrict__ bias, float* __restrict__ C,
    int M, int nkc)
{
    extern __shared__ float gsm[];
    __shared__ __align__(8) unsigned long long mb[2];
    int tid = threadIdx.x;
    int warp = tid >> 5, lane = tid & 31;
    int nt = blockIdx.x, mt = blockIdx.y;
    int warp_m = (warp >> 1) * 64, warp_n = (warp & 1) * 64;
    int m64w = warp >> 1, n64w = warp & 1;
    int gid = lane >> 2, tig = lane & 3;

    uint32_t mb0 = smem_u32(&mb[0]);
    uint32_t sm0 = smem_u32(gsm);

    if (tid == 0) { mbar_init(mb0, 1); mbar_init(mb0 + 8, 1); }
    __syncthreads();

    const float* Abase = AF + (size_t)mt * nkc * ABLKF;
    const float* Bbase = BF + (size_t)nt * nkc * BBLKF;

    if (tid == 0) {
        mbar_expect(mb0, BUFF * 4);
        bulk_cp(mb0, sm0, Abase, ABLKF * 4);
        bulk_cp(mb0, sm0 + ABLKF * 4, Bbase, BBLKF * 4);
    }

    float d[4][8][4];
#pragma unroll
    for (int i = 0; i < 4; i++)
#pragma unroll
        for (int j = 0; j < 8; j++)
#pragma unroll
            for (int q = 0; q < 4; q++) d[i][j][q] = 0.f;

    uint32_t ph = 0;
    int buf = 0;
    for (int kc = 0; kc < nkc; kc++) {
        mbar_wait(mb0 + buf * 8, (ph >> buf) & 1u);
        ph ^= (1u << buf);
        __syncthreads();
        if (tid == 0 && kc + 1 < nkc) {
            int nb = buf ^ 1;
            mbar_expect(mb0 + nb * 8, BUFF * 4);
            bulk_cp(mb0 + nb * 8, sm0 + nb * BUFF * 4,
                    Abase + (size_t)(kc + 1) * ABLKF, ABLKF * 4);
            bulk_cp(mb0 + nb * 8, sm0 + nb * BUFF * 4 + ABLKF * 4,
                    Bbase + (size_t)(kc + 1) * BBLKF, BBLKF * 4);
        }
        const float* Ab = gsm + buf * BUFF;
        const float* Bb = Ab + ABLKF;
#pragma unroll
        for (int k8 = 0; k8 < 4; k8++) {
            float af[16], bf[16];
            const float* ap = Ab + (k8 * 4 + m64w) * 640 + lane * 20;
            const float* bp = Bb + (k8 * 2 + n64w) * 640 + lane * 20;
#pragma unroll
            for (int p = 0; p < 4; p++) {
                *(float4*)&af[p * 4] = *(const float4*)(ap + p * 4);
                *(float4*)&bf[p * 4] = *(const float4*)(bp + p * 4);
            }
#pragma unroll
            for (int i = 0; i < 4; i++) {
#pragma unroll
                for (int j = 0; j < 8; j++) {
                    asm("mma.sync.aligned.m16n8k8.row.col.f32.tf32.tf32.f32 "
                        "{%0,%1,%2,%3}, {%4,%5,%6,%7}, {%8,%9}, {%0,%1,%2,%3};"
                        : "+f"(d[i][j][0]), "+f"(d[i][j][1]),
                          "+f"(d[i][j][2]), "+f"(d[i][j][3])
                        : "r"(__float_as_uint(af[i * 4 + 0])),
                          "r"(__float_as_uint(af[i * 4 + 1])),
                          "r"(__float_as_uint(af[i * 4 + 2])),
                          "r"(__float_as_uint(af[i * 4 + 3])),
                          "r"(__float_as_uint(bf[j * 2 + 0])),
                          "r"(__float_as_uint(bf[j * 2 + 1])));
                }
            }
        }
        buf ^= 1;
    }

#pragma unroll
    for (int i = 0; i < 4; i++) {
        int mr0 = mt * 256 + warp_m + i * 16 + gid;
        int mr1 = mr0 + 8;
#pragma unroll
        for (int j = 0; j < 8; j++) {
            int nc = nt * 128 + warp_n + j * 8 + tig * 2;
            float b0 = bias[nc], b1 = bias[nc + 1];
            if (mr0 < M) {
                C[(size_t)mr0 * GG + nc]     = d[i][j][0] + b0;
                C[(size_t)mr0 * GG + nc + 1] = d[i][j][1] + b1;
            }
            if (mr1 < M) {
                C[(size_t)mr1 * GG + nc]     = d[i][j][2] + b0;
                C[(size_t)mr1 * GG + nc + 1] = d[i][j][3] + b1;
            }
        }
    }
}

// ------------------- persistent LSTM: warp-per-unit, register cell state -------------------
#define NCTA_DIR 64
#define HCHUNK_BYTES (128 * BB * 4)
#define PRE_SLICE_B (48 * BB * 4)

__device__ __forceinline__ void dir_barrier(int dir) {
    __threadfence();
    __syncthreads();
    if (threadIdx.x == 0) {
        unsigned my = *(volatile unsigned*)&g_gen[dir];
        unsigned t = atomicAdd(&g_cnt[dir], 1u);
        if (t == NCTA_DIR - 1) {
            g_cnt[dir] = 0;
            __threadfence();
            atomicAdd(&g_gen[dir], 1u);
        } else {
            while (*(volatile unsigned*)&g_gen[dir] == my) { __nanosleep(64); }
            __threadfence();
        }
    }
    __syncthreads();
}

// 384 threads = 12 warps; warp w owns hidden unit U0+w (all 4 gates).
// W smem: pair-interleaved per unit: w2[(w*2+p)*1536 + k*2 + q] = W[(2p+q)*12+w][k]
__global__ __launch_bounds__(384) void lstm_persist_kernel(
    const float* __restrict__ preF, const float* __restrict__ preR,
    const float* __restrict__ whhF, const float* __restrict__ whhR,
    float* __restrict__ hout)
{
    extern __shared__ float sm[];
    float* w2_s  = sm;                       // 48*768 = 36864 floats
    float* h_s   = w2_s + 48 * DD;           // 3*128*32 ring = 12288
    float* pre_s = h_s + 3 * 128 * BB;       // 2*1536 [slot][b*48 + g*12 + u]
    __shared__ __align__(8) unsigned long long mbar_arr[5];

    int tid = threadIdx.x, bid = blockIdx.x;
    int dir = bid >> 6;
    int cta = bid & 63;
    int U0 = cta * 12;
    const float* whh = dir ? whhR : whhF;
    const float* pre = dir ? preR : preF;

    int w = tid >> 5, lane = tid & 31;       // warp = unit, lane = batch

    uint32_t mbar0 = smem_u32(&mbar_arr[0]);
    uint32_t hsm0  = smem_u32(h_s);
    uint32_t psm0  = smem_u32(pre_s);

    if (tid == 0) {
        for (int i = 0; i < 5; i++) mbar_init(mbar0 + i * 8, 1);
        int t0 = dir ? (WW - 1) : 0;
        mbar_expect(mbar0 + 3 * 8, PRE_SLICE_B);
        for (int b = 0; b < BB; b++)
            bulk_cp(mbar0 + 3 * 8, psm0 + b * 192,
                    pre + ((size_t)b * WW + t0) * GG + cta * 48, 192);
    }

    // W load: source row rr = g*12+u  ->  storage row sr = u*2 + (g>>1), q = g&1
    for (int idx = tid; idx < 48 * (DD / 4); idx += 384) {
        int rr = idx / (DD / 4), k4 = idx % (DD / 4);
        int g = rr / 12, u = rr % 12;
        int sr = u * 2 + (g >> 1), q = g & 1;
        float4 v = *(const float4*)(whh + ((size_t)(g * DD + U0 + u)) * DD + k4 * 4);
        float* base = &w2_s[sr * (2 * DD) + (k4 * 4) * 2 + q];
        base[0] = v.x; base[2] = v.y; base[4] = v.z; base[6] = v.w;
    }
    __syncthreads();

    float creg = 0.f;          // cell state for (unit w, batch lane)
    uint32_t phbits = 0;
    uint32_t preph = 0;

    for (int s = 0; s < WW; ++s) {
        int t = dir ? (WW - 1 - s) : s;

        if (tid == 0 && s + 1 < WW) {
            int tn = dir ? (WW - 2 - s) : (s + 1);
            int slot = (s + 1) & 1;
            mbar_expect(mbar0 + (3 + slot) * 8, PRE_SLICE_B);
            for (int b = 0; b < BB; b++)
                bulk_cp(mbar0 + (3 + slot) * 8, psm0 + slot * PRE_SLICE_B + b * 192,
                        pre + ((size_t)b * WW + tn) * GG + cta * 48, 192);
        }

        ull acc2[2] = {0ull, 0ull};   // pair0 = (i,f), pair1 = (g,o)

        if (s > 0) {
            const char* hsrc = (const char*)&g_hT[(s - 1) & 1][dir][0][0];
            if (tid == 0) {
                asm volatile("fence.proxy.async;" ::: "memory");
                mbar_expect(mbar0 + 0, HCHUNK_BYTES);
                bulk_cp(mbar0 + 0, hsm0, hsrc, HCHUNK_BYTES);
                mbar_expect(mbar0 + 8, HCHUNK_BYTES);
                bulk_cp(mbar0 + 8, hsm0 + HCHUNK_BYTES, hsrc + HCHUNK_BYTES, HCHUNK_BYTES);
            }
#pragma unroll 1
            for (int c = 0; c < 6; c++) {
                int slot = c % 3;
                mbar_wait(mbar0 + slot * 8, (phbits >> slot) & 1u);
                phbits ^= (1u << slot);
                __syncthreads();   // prior consumers of refill-target slot done
                if (tid == 0 && c < 4) {
                    int s2 = (c + 2) % 3;
                    mbar_expect(mbar0 + s2 * 8, HCHUNK_BYTES);
                    bulk_cp(mbar0 + s2 * 8, hsm0 + s2 * HCHUNK_BYTES,
                            hsrc + (size_t)(c + 2) * HCHUNK_BYTES, HCHUNK_BYTES);
                }
                const float* hb = h_s + slot * (128 * BB);
#pragma unroll 4
                for (int kk = 0; kk < 128; kk += 4) {
                    float h0 = hb[(kk + 0) * BB + lane];
                    float h1 = hb[(kk + 1) * BB + lane];
                    float h2v = hb[(kk + 2) * BB + lane];
                    float h3 = hb[(kk + 3) * BB + lane];
                    ull hp0 = packf2(h0, h0), hp1 = packf2(h1, h1);
                    ull hp2 = packf2(h2v, h2v), hp3 = packf2(h3, h3);
#pragma unroll
                    for (int p = 0; p < 2; p++) {
                        const float* wb = &w2_s[(w * 2 + p) * (2 * DD) + (c * 128 + kk) * 2];
                        ulonglong2 wv0 = *(const ulonglong2*)(wb);
                        ulonglong2 wv1 = *(const ulonglong2*)(wb + 4);
                        acc2[p] = fma2(wv0.x, hp0, acc2[p]);
                        acc2[p] = fma2(wv0.y, hp1, acc2[p]);
                        acc2[p] = fma2(wv1.x, hp2, acc2[p]);
                        acc2[p] = fma2(wv1.y, hp3, acc2[p]);
                    }
                }
            }
        }

        // wait for this step's pre slice (no block sync needed: warp-local cell)
        {
            int slot = s & 1;
            mbar_wait(mbar0 + (3 + slot) * 8, (preph >> slot) & 1u);
            preph ^= (1u << slot);
        }

        // warp-local LSTM cell: lane = batch, unit = w
        {
            const float* ps = pre_s + (s & 1) * (48 * BB) + lane * 48;
            float2 v0 = unpackf2(acc2[0]);   // (i, f) recurrent parts
            float2 v1 = unpackf2(acc2[1]);   // (g, o)
            float gi = ps[0 * 12 + w] + v0.x;
            float gf = ps[1 * 12 + w] + v0.y;
            float gg = ps[2 * 12 + w] + v1.x;
            float go = ps[3 * 12 + w] + v1.y;
            float iv = 1.f / (1.f + expf(-gi));
            float fv = 1.f / (1.f + expf(-gf));
            float gv = tanhf(gg);
            float ov = 1.f / (1.f + expf(-go));
            float cc = fv * creg + iv * gv;
            creg = cc;
            float hh = ov * tanhf(cc);
            __stcg(&g_hT[s & 1][dir][U0 + w][lane], hh);
            hout[((size_t)(lane * WW + t)) * H2 + dir * DD + U0 + w] = hh;
        }

        if (s < WW - 1) dir_barrier(dir);
    }
}

// ------------------- emissions: linear (NT=2) + softmax -------------------
__global__ void emis_kernel(const float* __restrict__ h2,
                            const float* __restrict__ wlin,
                            const float* __restrict__ blin,
                            float* __restrict__ out)
{
    int row = blockIdx.x * 8 + (threadIdx.x >> 5);
    int lane = threadIdx.x & 31;
    if (row >= MROWS) return;
    const float4* hr = (const float4*)(h2 + (size_t)row * H2);
    const float4* w0 = (const float4*)(wlin);
    const float4* w1 = (const float4*)(wlin + H2);
    float a0 = 0.f, a1 = 0.f;
    for (int i = lane; i < H2 / 4; i += 32) {
        float4 hv = hr[i], x0 = w0[i], x1 = w1[i];
        a0 += hv.x * x0.x + hv.y * x0.y + hv.z * x0.z + hv.w * x0.w;
        a1 += hv.x * x1.x + hv.y * x1.y + hv.z * x1.z + hv.w * x1.w;
    }
#pragma unroll
    for (int o = 16; o; o >>= 1) {
        a0 += __shfl_down_sync(0xffffffffu, a0, o);
        a1 += __shfl_down_sync(0xffffffffu, a1, o);
    }
    if (lane == 0) {
        float l0 = a0 + blin[0], l1 = a1 + blin[1];
        float m = fmaxf(l0, l1);
        float e0 = expf(l0 - m), e1 = expf(l1 - m);
        float inv = 1.f / (e0 + e1);
        float p0 = e0 * inv, p1 = e1 * inv;
        g_emis[row * 2] = p0; g_emis[row * 2 + 1] = p1;
        out[MROWS + row * 2] = p0; out[MROWS + row * 2 + 1] = p1;
    }
}

// ------------------- CRF -------------------
__device__ __forceinline__ float lse2(float x, float y) {
    float m = fmaxf(x, y);
    return m + log1pf(expf(fminf(x, y) - m));
}

__global__ void crf_llh_kernel(const int* __restrict__ labels,
                               const float* __restrict__ start,
                               const float* __restrict__ endv,
                               const float* __restrict__ trans,
                               float* __restrict__ out)
{
    int b = threadIdx.x;
    __shared__ float red[BB];
    int mul = g_w64 ? 2 : 1;
    const int* lab = labels + (size_t)b * WW * mul;
    float t00 = trans[0], t01 = trans[1], t10 = trans[2], t11 = trans[3];

    int prev = lab[0];
    float num = start[prev];
    for (int s = 0; s < WW; s++) {
        int tg = lab[s * mul];
        num += g_emis[(b * WW + s) * 2 + tg];
        if (s > 0) num += trans[prev * 2 + tg];
        prev = tg;
    }
    num += endv[prev];

    float a0 = start[0] + g_emis[(b * WW) * 2 + 0];
    float a1 = start[1] + g_emis[(b * WW) * 2 + 1];
    for (int s = 1; s < WW; s++) {
        float e0 = g_emis[(b * WW + s) * 2 + 0];
        float e1 = g_emis[(b * WW + s) * 2 + 1];
        float x0 = lse2(a0 + t00, a1 + t10) + e0;
        float x1 = lse2(a0 + t01, a1 + t11) + e1;
        a0 = x0; a1 = x1;
    }
    float logZ = lse2(a0 + endv[0], a1 + endv[1]);
    red[b] = num - logZ;
    __syncthreads();
    if (b == 0) {
        float sum = 0.f;
        for (int i = 0; i < BB; i++) sum += red[i];
        out[MROWS + MROWS * 2] = -(sum / (float)BB);
    }
}

__global__ void crf_decode_kernel(const float* __restrict__ start,
                                  const float* __restrict__ endv,
                                  const float* __restrict__ trans,
                                  float* __restrict__ out)
{
    int b = threadIdx.x;
    float t00 = trans[0], t01 = trans[1], t10 = trans[2], t11 = trans[3];
    float s0 = start[0] + g_emis[(b * WW) * 2 + 0];
    float s1 = start[1] + g_emis[(b * WW) * 2 + 1];
    for (int s = 1; s < WW; s++) {
        float c00 = s0 + t00, c10 = s1 + t10;
        float c01 = s0 + t01, c11 = s1 + t11;
        unsigned char bp0 = (c10 > c00) ? 1 : 0;
        unsigned char bp1 = (c11 > c01) ? 1 : 0;
        float e0 = g_emis[(b * WW + s) * 2 + 0];
        float e1 = g_emis[(b * WW + s) * 2 + 1];
        float n0 = fmaxf(c00, c10) + e0;
        float n1 = fmaxf(c01, c11) + e1;
        g_bp[b][s][0] = bp0; g_bp[b][s][1] = bp1;
        s0 = n0; s1 = n1;
    }
    int tag = (s1 + endv[1] > s0 + endv[0]) ? 1 : 0;
    out[b * WW + (WW - 1)] = (float)tag;
    for (int s = WW - 1; s >= 1; s--) {
        tag = (int)g_bp[b][s][tag];
        out[b * WW + (s - 1)] = (float)tag;
    }
}

// ------------------- host launcher -------------------
extern "C" void kernel_launch(void* const* d_in, const int* in_sizes, int n_in,
                              void* d_out, int out_size)
{
    const float* bert      = (const float*)d_in[0];
    const int*   words     = (const int*)d_in[1];
    const int*   labels    = (const int*)d_in[2];
    const float* w_ih_l0   = (const float*)d_in[3];
    const float* w_hh_l0   = (const float*)d_in[4];
    const float* b_l0      = (const float*)d_in[5];
    const float* w_ih_l0r  = (const float*)d_in[6];
    const float* w_hh_l0r  = (const float*)d_in[7];
    const float* b_l0r     = (const float*)d_in[8];
    const float* w_ih_l1   = (const float*)d_in[9];
    const float* w_hh_l1   = (const float*)d_in[10];
    const float* b_l1      = (const float*)d_in[11];
    const float* w_ih_l1r  = (const float*)d_in[12];
    const float* w_hh_l1r  = (const float*)d_in[13];
    const float* b_l1r     = (const float*)d_in[14];
    const float* w_lin     = (const float*)d_in[15];
    const float* b_lin     = (const float*)d_in[16];
    const float* crf_start = (const float*)d_in[17];
    const float* crf_end   = (const float*)d_in[18];
    const float* crf_trans = (const float*)d_in[19];
    float* out = (float*)d_out;

    float *pfeat, *ppre0, *ppre1, *ph1, *ph2, *pa3, *pb3f, *pb3r, *pbp0, *pbp1;
    cudaGetSymbolAddress((void**)&pfeat, g_feat);
    cudaGetSymbolAddress((void**)&ppre0, g_pre0);
    cudaGetSymbolAddress((void**)&ppre1, g_pre1);
    cudaGetSymbolAddress((void**)&ph1, g_h1);
    cudaGetSymbolAddress((void**)&ph2, g_h2);
    cudaGetSymbolAddress((void**)&pa3, g_a3);
    cudaGetSymbolAddress((void**)&pb3f, g_b3f);
    cudaGetSymbolAddress((void**)&pb3r, g_b3r);
    cudaGetSymbolAddress((void**)&pbp0, g_bpm0);
    cudaGetSymbolAddress((void**)&pbp1, g_bpm1);

    // W 147456 + h ring 49152 + pre 12288 = 208896 B
    const int lstm_smem = (48 * DD + 3 * 128 * BB + 2 * 48 * BB) * 4;
    cudaFuncSetAttribute(lstm_persist_kernel,
                         cudaFuncAttributeMaxDynamicSharedMemorySize, lstm_smem);
    const int gemm_smem = 2 * BUFF * 4;   // 122880
    cudaFuncSetAttribute(mma_frag_kernel,
                         cudaFuncAttributeMaxDynamicSharedMemorySize, gemm_smem);

    detect_kernel<<<1, 256>>>(words);
    firstidx_kernel<<<(MROWS + 255) / 256, 256>>>(words);
    gather_kernel<<<MROWS, 192>>>(bert);

    dim3 ggrid(GG / 128, MP / 256);   // (24, 32)

    // ---- layer 0 projections (K=768, K3=2304, nkc=72) ----
    {
        int nkc = 3 * DD / 32;
        splitA_frag<<<dim3(nkc, MP / 256), 256>>>(pfeat, pa3, MROWS, DD, nkc);
        splitB_frag<<<dim3(nkc, GG / 128), 256>>>(w_ih_l0,  b_l0,  pb3f, pbp0, DD, nkc);
        splitB_frag<<<dim3(nkc, GG / 128), 256>>>(w_ih_l0r, b_l0r, pb3r, pbp1, DD, nkc);
        mma_frag_kernel<<<ggrid, 256, gemm_smem>>>(pa3, pb3f, pbp0, ppre0, MROWS, nkc);
        mma_frag_kernel<<<ggrid, 256, gemm_smem>>>(pa3, pb3r, pbp1, ppre1, MROWS, nkc);
    }

    lstm_persist_kernel<<<128, 384, lstm_smem>>>(ppre0, ppre1, w_hh_l0, w_hh_l0r, ph1);

    // ---- layer 1 projections (K=1536, K3=4608, nkc=144) ----
    {
        int nkc = 3 * H2 / 32;
        splitA_frag<<<dim3(nkc, MP / 256), 256>>>(ph1, pa3, MROWS, H2, nkc);
        splitB_frag<<<dim3(nkc, GG / 128), 256>>>(w_ih_l1,  b_l1,  pb3f, pbp0, H2, nkc);
        splitB_frag<<<dim3(nkc, GG / 128), 256>>>(w_ih_l1r, b_l1r, pb3r, pbp1, H2, nkc);
        mma_frag_kernel<<<ggrid, 256, gemm_smem>>>(pa3, pb3f, pbp0, ppre0, MROWS, nkc);
        mma_frag_kernel<<<ggrid, 256, gemm_smem>>>(pa3, pb3r, pbp1, ppre1, MROWS, nkc);
    }

    lstm_persist_kernel<<<128, 384, lstm_smem>>>(ppre0, ppre1, w_hh_l1, w_hh_l1r, ph2);

    emis_kernel<<<MROWS / 8, 256>>>(ph2, w_lin, b_lin, out);
    crf_llh_kernel<<<1, BB>>>(labels, crf_start, crf_end, crf_trans, out);
    crf_decode_kernel<<<1, BB>>>(crf_start, crf_end, crf_trans, out);
}